// round 11
// baseline (speedup 1.0000x reference)
#include <cuda_runtime.h>
#include <cuda_bf16.h>

#define NUM_DOCS   1000000
#define VOCAB      30522
#define NNZ        64000000
#define TOTAL4     (NNZ / 4)
#define Q_NNZ      32
#define SHARDS     4
#define TOP_K      100
#define RPS        250000
#define BUFCAP     20480           // candidates/shard: mean ~16.8K, sigma ~130
#define K2_THREADS 512
#define SLOTS      (BUFCAP / K2_THREADS)
#define SELCAP     256
#define HASH_MUL   2654435761u
#define HTAB       512
#define EMPTY_KEY  0xFFFFFFFFu
#define EMPTY64    0xFFFFFFFF00000000ull

#define K1_THREADS 512
#define K1_BPSM    3
#define K1_BLOCKS  (148 * K1_BPSM)                  // 444
#define NTHR       (K1_BLOCKS * K1_THREADS)         // 227328 (multiple of 16!)

// ---- device scratch (zero-init at load; kernels restore invariant per replay) --
// Slots [0, n) of g_cscore/g_cand are rewritten every replay (n deterministic);
// slots beyond are never written and stay 0 from static init.
__device__ int   g_cand[SHARDS * BUFCAP];
__device__ float g_cscore[SHARDS * BUFCAP];
__device__ int   g_cnt[SHARDS];
__device__ float g_top_s[SHARDS * TOP_K];
__device__ int   g_top_i[SHARDS * TOP_K];
__device__ int   g_done;

// ---------------- K1: scoring with in-warp per-doc reduction --------------------
// Layout fact: c = blk*512 + warp*32 + lane + u*NTHR, and 512, 32, NTHR are all
// multiples of 16 -> a doc's 16 int4 chunks occupy 16 CONSECUTIVE LANES of one
// warp. So the doc score is finished right here with 4 bfly shuffles; final
// (score, doc) pairs append straight to the per-shard candidate list. No global
// score array, no gather pass.
__global__ void __launch_bounds__(K1_THREADS, K1_BPSM) score_kernel(
    const float* __restrict__ dv,
    const int*   __restrict__ di,
    const float* __restrict__ qv,
    const int*   __restrict__ qi)
{
    __shared__ unsigned long long tab[HTAB];   // 4 KB: (idx<<32 | value_bits)
    const int tid  = threadIdx.x;
    const int lane = tid & 31;

    for (int i = tid; i < HTAB; i += K1_THREADS) tab[i] = EMPTY64;
    __syncthreads();
    if (tid < Q_NNZ) {
        unsigned key = (unsigned)qi[tid];
        float val = qv[tid];
        unsigned h = ((key * HASH_MUL) >> 23) & (HTAB - 1);
        unsigned long long des = ((unsigned long long)key << 32)
                               | (unsigned long long)__float_as_uint(val);
        while (true) {
            unsigned long long old = atomicCAS(&tab[h], EMPTY64, des);
            if (old == EMPTY64) break;
            if ((unsigned)(old >> 32) == key) {      // duplicate term: coalesce sum
                atomicAdd((float*)&tab[h], val);     // low word = value
                break;
            }
            h = (h + 1) & (HTAB - 1);
        }
    }
    unsigned long long bloom = 0ull;               // 64-bit register bloom
    #pragma unroll
    for (int t = 0; t < Q_NNZ; t++)
        bloom |= 1ull << (((unsigned)__ldg(&qi[t]) * HASH_MUL) >> 26);
    __syncthreads();

    const int4* di4 = (const int4*)di;
    const int gid = blockIdx.x * K1_THREADS + tid;

    for (int c0 = gid; c0 < TOTAL4; c0 += NTHR * 4) {
        // front-batched loads (4 x LDG.128 in flight) — R4's proven pattern
        int4 v[4];
        int cs[4];
        #pragma unroll
        for (int u = 0; u < 4; u++) {
            int c = c0 + u * NTHR;
            cs[u] = c;
            v[u] = (c < TOTAL4) ? __ldcs(&di4[c]) : make_int4(-1, -1, -1, -1);
        }
        #pragma unroll
        for (int u = 0; u < 4; u++) {
            int idxs[4] = {v[u].x, v[u].y, v[u].z, v[u].w};
            float part = 0.0f;                      // this lane's 4-element partial
            #pragma unroll
            for (int j = 0; j < 4; j++) {
                unsigned idx = (unsigned)idxs[j];
                if ((bloom >> ((idx * HASH_MUL) >> 26)) & 1ull) {   // ~39% pass
                    unsigned h = ((idx * HASH_MUL) >> 23) & (HTAB - 1);
                    float qq = 0.0f;
                    #pragma unroll 1
                    while (true) {                  // ~1 probe on average
                        unsigned long long e = tab[h];
                        unsigned k = (unsigned)(e >> 32);
                        if (k == idx) { qq = __uint_as_float((unsigned)e); break; }
                        if (k == EMPTY_KEY) break;  // (pads also end here, qq=0)
                        h = (h + 1) & (HTAB - 1);
                    }
                    if (qq != 0.0f) {               // true hit (~0.1%)
                        part += __ldg(&dv[(cs[u] << 2) + j]) * qq;
                    }
                }
            }
            // warp-uniform gate: reduce + append only if some lane hit
            unsigned any = __ballot_sync(0xFFFFFFFFu, part != 0.0f);
            if (any) {                              // ~6.5% of warp-iterations
                float tot = part;                   // segmented 16-lane reduction
                tot += __shfl_xor_sync(0xFFFFFFFFu, tot, 8);
                tot += __shfl_xor_sync(0xFFFFFFFFu, tot, 4);
                tot += __shfl_xor_sync(0xFFFFFFFFu, tot, 2);
                tot += __shfl_xor_sync(0xFFFFFFFFu, tot, 1);
                if ((lane & 15) == 0 && tot != 0.0f && cs[u] < TOTAL4) {
                    int doc = cs[u] >> 4;           // 16 int4 chunks per doc
                    int sh = doc / RPS;
                    int p = atomicAdd(&g_cnt[sh], 1);
                    if (p < BUFCAP) {
                        g_cand[sh * BUFCAP + p]   = doc;
                        g_cscore[sh * BUFCAP + p] = tot;
                    }
                }
            }
        }
    }
}

// ---------------- K2: per-shard top-100 (register cache) + fused merge ----------
__device__ __forceinline__ int block_count(int local, int* red) {
    int w = __reduce_add_sync(0xFFFFFFFFu, local);
    int warp = threadIdx.x >> 5;
    int lane = threadIdx.x & 31;
    if (lane == 0) red[warp] = w;
    __syncthreads();
    if (threadIdx.x == 0) {
        int t = 0;
        #pragma unroll
        for (int i = 0; i < K2_THREADS / 32; i++) t += red[i];
        red[32] = t;
    }
    __syncthreads();
    int total = red[32];
    __syncthreads();
    return total;
}

__global__ void __launch_bounds__(K2_THREADS) topk_merge_kernel(float* __restrict__ out) {
    __shared__ int red[33];
    __shared__ unsigned long long s_sel[SELCAP];
    __shared__ int s_num;
    __shared__ int s_last;

    const int s = blockIdx.x;
    const int tid = threadIdx.x;
    int n = g_cnt[s]; if (n > BUFCAP) n = BUFCAP;

    unsigned sx[SLOTS];   // 40 x 32-bit score words; pad slots are 0
    #pragma unroll
    for (int k = 0; k < SLOTS; k++)
        sx[k] = __float_as_uint(g_cscore[s * BUFCAP + tid + k * K2_THREADS]);
    if (tid == 0) s_num = 0;
    __syncthreads();

    unsigned thr;
    if (n >= TOP_K) {
        unsigned lo = 0u, hi = 0x7F800000u;
        while (hi - lo > 1u) {
            unsigned mid = lo + ((hi - lo) >> 1);
            int local = 0;
            #pragma unroll
            for (int k = 0; k < SLOTS; k++) local += (sx[k] >= mid) ? 1 : 0;
            int c = block_count(local, red);
            if (c >= TOP_K) lo = mid; else hi = mid;
        }
        thr = (lo == 0u) ? 1u : lo;    // exclude zero pads
    } else {
        thr = 1u;                      // degenerate (never with this data)
    }

    // compact; key = (score_bits<<32) | (~local_doc): tie -> lower doc index
    #pragma unroll
    for (int k = 0; k < SLOTS; k++) {
        if (sx[k] >= thr) {
            int i = tid + k * K2_THREADS;
            int doc = g_cand[s * BUFCAP + i];
            int p = atomicAdd(&s_num, 1);
            if (p < SELCAP)
                s_sel[p] = ((unsigned long long)sx[k] << 32)
                         | (unsigned long long)(0xFFFFFFFFu - (unsigned)(doc - s * RPS));
        }
    }
    __syncthreads();
    int m = s_num; if (m > SELCAP) m = SELCAP;
    if (tid < m) {
        unsigned long long key = s_sel[tid];
        int rank = 0;
        for (int j = 0; j < m; j++) rank += (s_sel[j] > key) ? 1 : 0;
        if (rank < TOP_K) {
            g_top_s[s * TOP_K + rank] = __uint_as_float((unsigned)(key >> 32));
            g_top_i[s * TOP_K + rank] = s * RPS
                + (int)(0xFFFFFFFFu - (unsigned)(key & 0xFFFFFFFFull));
        }
    }
    if (tid >= m && tid < TOP_K) {       // degenerate pad (unreachable)
        g_top_s[s * TOP_K + tid] = 0.0f;
        g_top_i[s * TOP_K + tid] = s * RPS + tid;
    }
    if (tid == 0) g_cnt[s] = 0;          // reset for next replay

    // ---- fused merge in the last-arriving block ----
    __threadfence();
    __syncthreads();
    if (tid == 0) {
        int old = atomicAdd(&g_done, 1);
        s_last = (old == SHARDS - 1) ? 1 : 0;
    }
    __syncthreads();
    if (!s_last) return;
    __threadfence();

    __shared__ unsigned long long k400[SHARDS * TOP_K];
    __shared__ float sc400[SHARDS * TOP_K];
    __shared__ int   id400[SHARDS * TOP_K];
    for (int p = tid; p < SHARDS * TOP_K; p += K2_THREADS) {
        float sc = __ldcg(&g_top_s[p]);
        int   id = __ldcg(&g_top_i[p]);
        k400[p] = ((unsigned long long)__float_as_uint(sc) << 32)
                | (unsigned long long)(0xFFFFFFFFu - (unsigned)p);  // tie: lower pos
        sc400[p] = sc;
        id400[p] = id;
    }
    __syncthreads();
    if (tid < SHARDS * TOP_K) {
        unsigned long long key = k400[tid];
        int rank = 0;
        #pragma unroll 4
        for (int j = 0; j < SHARDS * TOP_K; j++) rank += (k400[j] > key) ? 1 : 0;
        if (rank < TOP_K) {
            out[rank]         = sc400[tid];
            out[TOP_K + rank] = (float)id400[tid];
        }
    }
    if (tid == 0) g_done = 0;
}

// ---------------- launch --------------------------------------------------------
extern "C" void kernel_launch(void* const* d_in, const int* in_sizes, int n_in,
                              void* d_out, int out_size) {
    const float* dv = (const float*)d_in[0];   // doc_values   [NNZ]
    const float* qv = (const float*)d_in[1];   // q_values     [Q_NNZ]
    const int*   di = (const int*)  d_in[2];   // doc_indices  [NNZ]
    /* d_in[3] = row_ids: redundant, never read */
    const int*   qi = (const int*)  d_in[4];   // q_indices    [Q_NNZ]
    float* out = (float*)d_out;

    score_kernel<<<K1_BLOCKS, K1_THREADS>>>(dv, di, qv, qi);
    topk_merge_kernel<<<SHARDS, K2_THREADS>>>(out);
}

// round 12
// speedup vs baseline: 1.9460x; 1.9460x over previous
#include <cuda_runtime.h>
#include <cuda_bf16.h>

#define NUM_DOCS   1000000
#define VOCAB      30522
#define VOCABP     (VOCAB + 1)     // +1 sentinel slot (always 0) for pad indices
#define NNZ        64000000
#define Q_NNZ      32
#define SHARDS     4
#define TOP_K      100
#define RPS        250000
#define BUFCAP     20480           // candidates/shard: mean ~16.8K, sigma ~130
#define K2_THREADS 512
#define SLOTS      (BUFCAP / K2_THREADS)
#define SELCAP     1024            // selection buffer (threshold-bin ties included)
#define GATHER_THREADS 512
#define GATHER_BLOCKS  (SHARDS * BUFCAP / GATHER_THREADS)   // 160
#define NBINS      4096            // score-bits >> 19

// ---- device scratch (zero-init at load; kernels restore invariant per replay) --
__device__ float g_scores[NUM_DOCS];
__device__ int   g_cand[SHARDS * BUFCAP];
__device__ float g_cscore[SHARDS * BUFCAP];
__device__ int   g_cnt[SHARDS];
__device__ float g_top_s[SHARDS * TOP_K];
__device__ int   g_top_i[SHARDS * TOP_K];
__device__ int   g_done;

// ---------------- K1: scoring (R4 verbatim -- best measured: 2562 GB/s) ---------
__global__ void __launch_bounds__(1024, 1) score_kernel(
    const float* __restrict__ dv,
    const int*   __restrict__ di,
    const float* __restrict__ qv,
    const int*   __restrict__ qi)
{
    extern __shared__ float q[];   // VOCABP floats; q[VOCAB] = 0 sentinel
    for (int i = threadIdx.x; i < VOCABP; i += blockDim.x) q[i] = 0.0f;
    __syncthreads();
    if (threadIdx.x < Q_NNZ) atomicAdd(&q[qi[threadIdx.x]], qv[threadIdx.x]);
    __syncthreads();

    const int4* di4 = (const int4*)di;
    const int total4 = NNZ / 4;
    const int stride = gridDim.x * blockDim.x;
    const int step = 4 * stride;
    const int4 PAD = make_int4(VOCAB, VOCAB, VOCAB, VOCAB);

    int c0 = blockIdx.x * blockDim.x + threadIdx.x;

    int4 p0 = (c0              < total4) ? __ldcs(&di4[c0])              : PAD;
    int4 p1 = (c0 + stride     < total4) ? __ldcs(&di4[c0 + stride])     : PAD;
    int4 p2 = (c0 + 2 * stride < total4) ? __ldcs(&di4[c0 + 2 * stride]) : PAD;
    int4 p3 = (c0 + 3 * stride < total4) ? __ldcs(&di4[c0 + 3 * stride]) : PAD;

    while (c0 < total4) {
        int cn = c0 + step;
        int4 n0 = (cn              < total4) ? __ldcs(&di4[cn])              : PAD;
        int4 n1 = (cn + stride     < total4) ? __ldcs(&di4[cn + stride])     : PAD;
        int4 n2 = (cn + 2 * stride < total4) ? __ldcs(&di4[cn + 2 * stride]) : PAD;
        int4 n3 = (cn + 3 * stride < total4) ? __ldcs(&di4[cn + 3 * stride]) : PAD;

        float a0 = (q[p0.x] + q[p0.y]) + (q[p0.z] + q[p0.w]);
        float a1 = (q[p1.x] + q[p1.y]) + (q[p1.z] + q[p1.w]);
        float a2 = (q[p2.x] + q[p2.y]) + (q[p2.z] + q[p2.w]);
        float a3 = (q[p3.x] + q[p3.y]) + (q[p3.z] + q[p3.w]);

        if (((a0 + a1) + (a2 + a3)) != 0.0f) {
            #pragma unroll
            for (int k = 0; k < 4; k++) {
                int cc = c0 + k * stride;
                int4 v = (k == 0) ? p0 : (k == 1) ? p1 : (k == 2) ? p2 : p3;
                int idx[4] = {v.x, v.y, v.z, v.w};
                #pragma unroll
                for (int j = 0; j < 4; j++) {
                    float qq = q[idx[j]];
                    if (qq != 0.0f) {
                        float contrib = __ldcs(&dv[cc * 4 + j]) * qq;
                        int doc = cc >> 4;           // 16 int4 chunks per doc
                        float old = atomicAdd(&g_scores[doc], contrib);
                        if (old == 0.0f && contrib > 0.0f) {   // exactly-once
                            int sh = doc / RPS;
                            int p = atomicAdd(&g_cnt[sh], 1);
                            if (p < BUFCAP) g_cand[sh * BUFCAP + p] = doc;
                        }
                    }
                }
            }
        }
        p0 = n0; p1 = n1; p2 = n2; p3 = n3;
        c0 = cn;
    }
}

// ---------------- K2a: full-chip scatter -> coalesced gather (R4 verbatim) ------
__global__ void __launch_bounds__(GATHER_THREADS) gather_kernel() {
    int i = blockIdx.x * GATHER_THREADS + threadIdx.x;
    int s = i / BUFCAP;
    int j = i - s * BUFCAP;
    int n = g_cnt[s]; if (n > BUFCAP) n = BUFCAP;
    float sc = 0.0f;
    if (j < n) {
        int doc = g_cand[i];
        sc = g_scores[doc];
        g_scores[doc] = 0.0f;    // restore replay invariant
    }
    g_cscore[i] = sc;            // coalesced; pads 0
}

// ---------------- K2b: histogram-select top-100 + fused merge -------------------
__global__ void __launch_bounds__(K2_THREADS) topk_merge_kernel(float* __restrict__ out) {
    __shared__ int hist[NBINS];                 // 16 KB
    __shared__ unsigned long long s_sel[SELCAP];
    __shared__ int s_num;
    __shared__ int s_thrbin;
    __shared__ int s_last;

    const int s = blockIdx.x;
    const int tid = threadIdx.x;
    const int lane = tid & 31;
    int n = g_cnt[s]; if (n > BUFCAP) n = BUFCAP;

    // coalesced load of 40 score words/thread; pads are 0
    unsigned sx[SLOTS];
    #pragma unroll
    for (int k = 0; k < SLOTS; k++)
        sx[k] = __float_as_uint(g_cscore[s * BUFCAP + tid + k * K2_THREADS]);

    #pragma unroll
    for (int b = tid; b < NBINS; b += K2_THREADS) hist[b] = 0;
    if (tid == 0) { s_num = 0; s_thrbin = 1; }
    __syncthreads();

    // one-pass histogram on score bits >> 19 (monotone for positive floats)
    #pragma unroll
    for (int k = 0; k < SLOTS; k++)
        if (sx[k] != 0u) atomicAdd(&hist[sx[k] >> 19], 1);
    __syncthreads();

    // warp 0: suffix scan from the top; threshold bin B = largest bin with
    // suffix-count >= TOP_K  (exactly the binary search's answer)
    if (tid < 32 && n >= TOP_K) {
        int cum = 0;
        for (int base = NBINS - 32; base >= 0; base -= 32) {
            int v = hist[base + lane];
            int chunktot = __reduce_add_sync(0xFFFFFFFFu, v);
            if (cum + chunktot >= TOP_K) {
                int suf = v;                        // suffix within chunk
                #pragma unroll
                for (int off = 1; off < 32; off <<= 1) {
                    int t = __shfl_down_sync(0xFFFFFFFFu, suf, off);
                    if (lane + off < 32) suf += t;
                }
                unsigned ok = __ballot_sync(0xFFFFFFFFu, cum + suf >= TOP_K);
                if (lane == 0) s_thrbin = base + (31 - __clz(ok));
                break;
            }
            cum += chunktot;
        }
    }
    __syncthreads();
    unsigned thr = (n >= TOP_K) ? ((unsigned)s_thrbin << 19) : 1u;

    // compact selected; key = (score<<32) | (~local_doc): tie -> lower doc idx
    #pragma unroll
    for (int k = 0; k < SLOTS; k++) {
        if (sx[k] >= thr) {
            int i = tid + k * K2_THREADS;
            int doc = g_cand[s * BUFCAP + i];
            int p = atomicAdd(&s_num, 1);
            if (p < SELCAP)
                s_sel[p] = ((unsigned long long)sx[k] << 32)
                         | (unsigned long long)(0xFFFFFFFFu - (unsigned)(doc - s * RPS));
        }
    }
    __syncthreads();
    int m = s_num; if (m > SELCAP) m = SELCAP;
    if (tid < m) {
        unsigned long long key = s_sel[tid];
        int rank = 0;
        for (int j = 0; j < m; j++) rank += (s_sel[j] > key) ? 1 : 0;
        if (rank < TOP_K) {
            g_top_s[s * TOP_K + rank] = __uint_as_float((unsigned)(key >> 32));
            g_top_i[s * TOP_K + rank] = s * RPS
                + (int)(0xFFFFFFFFu - (unsigned)(key & 0xFFFFFFFFull));
        }
    }
    if (tid >= m && tid < TOP_K) {       // degenerate pad (unreachable)
        g_top_s[s * TOP_K + tid] = 0.0f;
        g_top_i[s * TOP_K + tid] = s * RPS + tid;
    }
    if (tid == 0) g_cnt[s] = 0;          // reset for next replay

    // ---- fused merge in the last-arriving block ----
    __threadfence();
    __syncthreads();
    if (tid == 0) {
        int old = atomicAdd(&g_done, 1);
        s_last = (old == SHARDS - 1) ? 1 : 0;
    }
    __syncthreads();
    if (!s_last) return;
    __threadfence();

    __shared__ unsigned long long k400[SHARDS * TOP_K];
    __shared__ float sc400[SHARDS * TOP_K];
    __shared__ int   id400[SHARDS * TOP_K];
    for (int p = tid; p < SHARDS * TOP_K; p += K2_THREADS) {
        float sc = __ldcg(&g_top_s[p]);
        int   id = __ldcg(&g_top_i[p]);
        k400[p] = ((unsigned long long)__float_as_uint(sc) << 32)
                | (unsigned long long)(0xFFFFFFFFu - (unsigned)p);  // tie: lower pos
        sc400[p] = sc;
        id400[p] = id;
    }
    __syncthreads();
    if (tid < SHARDS * TOP_K) {
        unsigned long long key = k400[tid];
        int rank = 0;
        #pragma unroll 4
        for (int j = 0; j < SHARDS * TOP_K; j++) rank += (k400[j] > key) ? 1 : 0;
        if (rank < TOP_K) {
            out[rank]         = sc400[tid];
            out[TOP_K + rank] = (float)id400[tid];
        }
    }
    if (tid == 0) g_done = 0;
}

// ---------------- launch --------------------------------------------------------
extern "C" void kernel_launch(void* const* d_in, const int* in_sizes, int n_in,
                              void* d_out, int out_size) {
    const float* dv = (const float*)d_in[0];   // doc_values   [NNZ]
    const float* qv = (const float*)d_in[1];   // q_values     [Q_NNZ]
    const int*   di = (const int*)  d_in[2];   // doc_indices  [NNZ]
    /* d_in[3] = row_ids: redundant, never read */
    const int*   qi = (const int*)  d_in[4];   // q_indices    [Q_NNZ]
    float* out = (float*)d_out;

    cudaFuncSetAttribute(score_kernel,
                         cudaFuncAttributeMaxDynamicSharedMemorySize, VOCABP * 4);

    score_kernel<<<148, 1024, VOCABP * 4>>>(dv, di, qv, qi);
    gather_kernel<<<GATHER_BLOCKS, GATHER_THREADS>>>();
    topk_merge_kernel<<<SHARDS, K2_THREADS>>>(out);
}